// round 11
// baseline (speedup 1.0000x reference)
#include <cuda_runtime.h>
#include <cuda_bf16.h>
#include <cstdint>
#include <math.h>

// Problem constants
#define BATCH   8192
#define DIM     1024      // DIM1 == DIM2
#define SKETCH  8192
#define OUT     512
#define LN_EPS  1e-5f

#define MCAP    1024      // |J| <= 1024 (hard bound)
#define CCH     128       // column chunk for main kernel
#define TB      64        // batch rows per CTA in main kernel
#define NTHR    1024      // threads per CTA (32 warps)
#define SUBCL   32        // W staging sub-chunk (32 cols x 512 x 4B = 64KB)

// dynamic smem layout (floats): sp[CCH*TB] + 2 x WS[SUBCL*OUT]
#define SP_OFF     0
#define WSA_OFF    (CCH * TB)
#define WSB_OFF    (WSA_OFF + SUBCL * OUT)
#define DSM_FLOATS (WSB_OFF + SUBCL * OUT)
#define DSM_BYTES  (DSM_FLOATS * 4)          // 160 KB

// ---------------- device globals (scratch; no cudaMalloc allowed) ----------
__device__ unsigned int g_idx1[DIM];
__device__ unsigned int g_idx2[DIM];
__device__ int          g_m;
__device__ int          g_fallback;       // 1 if any column has >4 entries
__device__ int          g_colJ[MCAP];
__device__ int          g_cp1[MCAP + 1];
__device__ int          g_cp2[MCAP + 1];
__device__ unsigned int g_ent1[MCAP];     // (sign<<15) | i
__device__ unsigned int g_ent2[MCAP];
__device__ ulonglong2   g_rec[MCAP];      // packed per-column records

// -------- f32x2 packed-FMA helpers (PTX-only) ------------------------------
__device__ __forceinline__ unsigned long long pack2(float lo, float hi) {
    unsigned long long r;
    asm("mov.b64 %0, {%1, %2};" : "=l"(r) : "f"(lo), "f"(hi));
    return r;
}
__device__ __forceinline__ void unpack2(unsigned long long v, float& lo, float& hi) {
    asm("mov.b64 {%0, %1}, %2;" : "=f"(lo), "=f"(hi) : "l"(v));
}
__device__ __forceinline__ unsigned long long ffma2(unsigned long long a,
                                                    unsigned long long b,
                                                    unsigned long long c) {
    unsigned long long d;
    asm("fma.rn.f32x2 %0, %1, %2, %3;" : "=l"(d) : "l"(a), "l"(b), "l"(c));
    return d;
}
// apply packed sign: e bit10 set -> negate (XOR into fp32 sign bit)
__device__ __forceinline__ float sgnapply(float x, unsigned e) {
    return __int_as_float(__float_as_int(x) ^ (int)((e & 1024u) << 21));
}

// -------- cp.async helpers -------------------------------------------------
__device__ __forceinline__ void cpasync16(unsigned int saddr, const float* gaddr) {
    asm volatile("cp.async.cg.shared.global [%0], [%1], 16;"
                 :: "r"(saddr), "l"(gaddr));
}
__device__ __forceinline__ void cpasync_commit() {
    asm volatile("cp.async.commit_group;");
}
__device__ __forceinline__ void cpasync_wait0() {
    asm volatile("cp.async.wait_group 0;");
}

// -------- warp-shuffle block scan (1024 threads, 2 internal barriers) ------
// Returns inclusive scan of val over the block. ws is a 32-int smem buffer;
// ws[31] holds the grand total after return. Caller must barrier before the
// next use of ws (all call sites below have intervening barriers).
__device__ __forceinline__ int block_scan_incl(int val, int t, int* ws) {
    const unsigned full = 0xFFFFFFFFu;
    int lane = t & 31;
#pragma unroll
    for (int o = 1; o < 32; o <<= 1) {
        int n = __shfl_up_sync(full, val, o);
        if (lane >= o) val += n;
    }
    if (lane == 31) ws[t >> 5] = val;
    __syncthreads();
    if (t < 32) {
        int v = ws[t];
#pragma unroll
        for (int o = 1; o < 32; o <<= 1) {
            int n = __shfl_up_sync(full, v, o);
            if (t >= o) v += n;
        }
        ws[t] = v;
    }
    __syncthreads();
    if (t >= 32) val += ws[(t >> 5) - 1];
    return val;
}

// ---------------------------------------------------------------------------
// Kernel A: find the single nonzero per row of S1/S2. Coalesced float4 scan.
// ---------------------------------------------------------------------------
__global__ void k_extract(const float* __restrict__ S1,
                          const float* __restrict__ S2)
{
    int row = blockIdx.x;
    const float* S;
    unsigned int* outp;
    if (row < DIM) { S = S1; outp = g_idx1; }
    else           { S = S2; outp = g_idx2; row -= DIM; }

    const float4* p = (const float4*)(S + (size_t)row * SKETCH);
    int t = threadIdx.x;
#pragma unroll
    for (int k = 0; k < SKETCH / 4 / 256; k++) {
        int v4 = t + k * 256;
        float4 v = p[v4];
        int base = v4 * 4;
        if (v.x != 0.0f) outp[row] = (unsigned)(base + 0) | (v.x < 0.0f ? 0x80000000u : 0u);
        if (v.y != 0.0f) outp[row] = (unsigned)(base + 1) | (v.y < 0.0f ? 0x80000000u : 0u);
        if (v.z != 0.0f) outp[row] = (unsigned)(base + 2) | (v.z < 0.0f ? 0x80000000u : 0u);
        if (v.w != 0.0f) outp[row] = (unsigned)(base + 3) | (v.w < 0.0f ? 0x80000000u : 0u);
    }
}

// ---------------------------------------------------------------------------
// Kernel B: build compact structure + CSR + packed records. 1 CTA, 1024 thr.
// Scans use warp shuffles (3 barriers each) instead of Kogge-Stone (~20).
// ---------------------------------------------------------------------------
__global__ void k_build()
{
    __shared__ int cnt[SKETCH];      // occupancy counts, then colmap
    __shared__ int colcnt[MCAP];
    __shared__ int ws[32];
    __shared__ int sh_total;

    int t = threadIdx.x;

    for (int j = t; j < SKETCH; j += 1024) cnt[j] = 0;
    if (t == 0) g_fallback = 0;
    __syncthreads();

    unsigned u1 = g_idx1[t];
    unsigned u2 = g_idx2[t];
    atomicAdd(&cnt[u1 & (SKETCH - 1)], 1);
    atomicAdd(&cnt[u2 & (SKETCH - 1)], 1 << 16);
    __syncthreads();

    // qualification: thread t owns j in [t*8, t*8+8)
    int q = 0;
    int qual[8];
#pragma unroll
    for (int u = 0; u < 8; u++) {
        int j = t * 8 + u;
        int c = cnt[j];
        qual[u] = ((c & 0xFFFF) > 0 && (c >> 16) > 0) ? 1 : 0;
        q += qual[u];
    }
    int incl = block_scan_incl(q, t, ws);
    int excl = incl - q;
    if (t == 1023) sh_total = incl;
    __syncthreads();
    int total = sh_total;

#pragma unroll
    for (int u = 0; u < 8; u++) {
        int j = t * 8 + u;
        if (qual[u]) { g_colJ[excl] = j; cnt[j] = excl; excl++; }
        else         { cnt[j] = -1; }
    }
    if (t == 0) g_m = total;
    __syncthreads();

    int c1 = cnt[u1 & (SKETCH - 1)];
    int c2 = cnt[u2 & (SKETCH - 1)];
#pragma unroll
    for (int s = 0; s < 2; s++) {
        int cc = s ? c2 : c1;
        unsigned uu = s ? u2 : u1;
        int* cp = s ? g_cp2 : g_cp1;
        unsigned int* ent = s ? g_ent2 : g_ent1;

        colcnt[t] = 0;
        __syncthreads();
        if (cc >= 0) atomicAdd(&colcnt[cc], 1);
        __syncthreads();

        int myc = colcnt[t];
        int inc2 = block_scan_incl(myc, t, ws);
        int ex = inc2 - myc;
        cp[t] = ex;
        if (t == 1023) cp[1024] = inc2;
        __syncthreads();
        colcnt[t] = ex;      // running offsets
        __syncthreads();
        if (cc >= 0) {
            int slot = atomicAdd(&colcnt[cc], 1);
            ent[slot] = (((uu >> 31) & 1u) << 15) | (unsigned)t;
        }
        __syncthreads();
    }

    // ---- packed records: per column, both sides, up to 4 entries ----
    if (t < total) {
        unsigned long long w[2];
#pragma unroll
        for (int s = 0; s < 2; s++) {
            const int* cp = s ? g_cp2 : g_cp1;
            const unsigned int* ent = s ? g_ent2 : g_ent1;
            int e0 = cp[t], e1 = cp[t + 1];
            int cnte = e1 - e0;
            if (cnte > 4) { atomicOr(&g_fallback, 1); cnte = 4; }
            unsigned long long u = 0;
            for (int k = 0; k < cnte; k++) {
                unsigned v = ent[e0 + k];
                unsigned i = v & 1023u;
                unsigned sg = (v >> 15) & 1u;
                u |= (unsigned long long)(i | (sg << 10)) << (11 * k);
            }
            u |= (unsigned long long)cnte << 60;
            w[s] = u;
        }
        ulonglong2 r;
        r.x = w[0];
        r.y = w[1];
        g_rec[t] = r;
    }
}

// ---------------------------------------------------------------------------
// GEMM micro-step (proven round-7 inner loop; wsbuf = staged W buffer)
// ---------------------------------------------------------------------------
#define GEMM_STEP(wsbuf, base, c2_)                                            \
    {                                                                          \
        float2 vv = *(const float2*)&sp[((base) + (c2_)) * TB + r0];           \
        unsigned long long v2a = pack2(vv.x, vv.x);                            \
        unsigned long long v2b = pack2(vv.y, vv.y);                            \
        const ulonglong2* wp = (const ulonglong2*)&(wsbuf)[(c2_) * OUT + o0];  \
        ulonglong2 w01 = wp[0];                                                \
        ulonglong2 w23 = wp[1];                                                \
        ulonglong2 w45 = wp[2];                                                \
        ulonglong2 w67 = wp[3];                                                \
        acc2[0][0] = ffma2(v2a, w01.x, acc2[0][0]);                            \
        acc2[1][0] = ffma2(v2b, w01.x, acc2[1][0]);                            \
        acc2[0][1] = ffma2(v2a, w01.y, acc2[0][1]);                            \
        acc2[1][1] = ffma2(v2b, w01.y, acc2[1][1]);                            \
        acc2[0][2] = ffma2(v2a, w23.x, acc2[0][2]);                            \
        acc2[1][2] = ffma2(v2b, w23.x, acc2[1][2]);                            \
        acc2[0][3] = ffma2(v2a, w23.y, acc2[0][3]);                            \
        acc2[1][3] = ffma2(v2b, w23.y, acc2[1][3]);                            \
        acc2[0][4] = ffma2(v2a, w45.x, acc2[0][4]);                            \
        acc2[1][4] = ffma2(v2b, w45.x, acc2[1][4]);                            \
        acc2[0][5] = ffma2(v2a, w45.y, acc2[0][5]);                            \
        acc2[1][5] = ffma2(v2b, w45.y, acc2[1][5]);                            \
        acc2[0][6] = ffma2(v2a, w67.x, acc2[0][6]);                            \
        acc2[1][6] = ffma2(v2b, w67.x, acc2[1][6]);                            \
        acc2[0][7] = ffma2(v2a, w67.y, acc2[0][7]);                            \
        acc2[1][7] = ffma2(v2b, w67.y, acc2[1][7]);                            \
    }

// ---------------------------------------------------------------------------
// Main fused kernel. TB=64 rows/CTA, 1024 threads (32 warps), 128 CTAs.
//  W staging: cp.async (LDGSTS) double-buffered, with colJ row indirection
//  directly from the original W (no k_wgather kernel). Sub-tile 0 is issued
//  BEFORE the gather so its copies overlap the gather's scattered loads;
//  sub-tile s+1 is issued before GEMM(s) and waited after it.
//  Gather (fast): packed records, 2 rows/thread (round-9 proven path).
//  Epilogue: LayerNorm (bias folded into acc init) + ReLU.
// ---------------------------------------------------------------------------
__global__ void __launch_bounds__(NTHR, 1)
k_main(const float* __restrict__ x1, const float* __restrict__ x2,
       const float* __restrict__ W, const float* __restrict__ bias,
       const float* __restrict__ gamma, const float* __restrict__ beta,
       float* __restrict__ out)
{
    extern __shared__ __align__(16) float dsm[];
    float* sp = dsm + SP_OFF;     // [CCH][TB] product tile; LN bufs alias
    float* WSbuf[2] = { dsm + WSA_OFF, dsm + WSB_OFF };

    int tid  = threadIdx.x;
    int lane = tid & 31;
    int wrp  = tid >> 5;          // 0..31 -> cols [wrp*16, wrp*16+16)
    int o0   = wrp * 16;
    int r0   = lane * 2;          // rows r0, r0+1
    int b0   = blockIdx.x * TB;

    int m  = g_m;
    int fb = g_fallback;

    // staging geometry: each thread copies 16 floats of one W row per stage
    int st_row = tid >> 5;            // 0..31
    int st_col = (tid & 31) * 16;     // 0..496

    // accumulators: acc2[p][k] = row (r0+p), cols (o0+2k, o0+2k+1)
    unsigned long long acc2[2][8];
    {
        const ulonglong2* bq = (const ulonglong2*)(bias + o0);
#pragma unroll
        for (int q = 0; q < 4; q++) {
            ulonglong2 bb = __ldg(bq + q);
            acc2[0][2 * q]     = bb.x;
            acc2[0][2 * q + 1] = bb.y;
            acc2[1][2 * q]     = bb.x;
            acc2[1][2 * q + 1] = bb.y;
        }
    }

    int nch = (m + CCH - 1) / CCH;
    for (int ch = 0; ch < nch; ch++) {
        int ck0 = ch * CCH;
        int Cn  = min(CCH, m - ck0);
        int nsub = (Cn + SUBCL - 1) / SUBCL;

        // ---- issue W sub-tile 0 (overlaps the gather below) ----
        {
            int cidx = ck0 + st_row;
            if (cidx >= m) cidx = m - 1;              // clamp (safe dup)
            int wrow = __ldg(&g_colJ[cidx]);
            const float* src = W + (size_t)wrow * OUT + st_col;
            unsigned int dst = (unsigned int)__cvta_generic_to_shared(
                                   WSbuf[0] + st_row * OUT + st_col);
            cpasync16(dst,      src);
            cpasync16(dst + 16, src + 4);
            cpasync16(dst + 32, src + 8);
            cpasync16(dst + 48, src + 12);
            cpasync_commit();
        }

        // ---- gather: v[c][r] = s1(c,r) * s2(c,r) ----
        if (!fb) {
            int nw = Cn * 32;
            for (int p = tid; p < nw; p += NTHR) {
                int cl = p >> 5;
                int r  = p & 31;
                int c  = ck0 + cl;
                ulonglong2 rec = __ldg(&g_rec[c]);
                size_t ro0 = (size_t)(b0 + r) * DIM;
                size_t ro1 = (size_t)(b0 + r + 32) * DIM;

                unsigned long long u = rec.x;
                int cnt1 = (int)(u >> 60);
                unsigned e = (unsigned)u & 0x7FFu;
                float s1a = sgnapply(__ldg(&x1[ro0 + (e & 1023u)]), e);
                float s1b = sgnapply(__ldg(&x1[ro1 + (e & 1023u)]), e);
#pragma unroll
                for (int k = 1; k < 4; k++) {
                    if (k < cnt1) {
                        e = (unsigned)(u >> (11 * k)) & 0x7FFu;
                        s1a += sgnapply(__ldg(&x1[ro0 + (e & 1023u)]), e);
                        s1b += sgnapply(__ldg(&x1[ro1 + (e & 1023u)]), e);
                    }
                }
                u = rec.y;
                int cnt2 = (int)(u >> 60);
                e = (unsigned)u & 0x7FFu;
                float s2a = sgnapply(__ldg(&x2[ro0 + (e & 1023u)]), e);
                float s2b = sgnapply(__ldg(&x2[ro1 + (e & 1023u)]), e);
#pragma unroll
                for (int k = 1; k < 4; k++) {
                    if (k < cnt2) {
                        e = (unsigned)(u >> (11 * k)) & 0x7FFu;
                        s2a += sgnapply(__ldg(&x2[ro0 + (e & 1023u)]), e);
                        s2b += sgnapply(__ldg(&x2[ro1 + (e & 1023u)]), e);
                    }
                }
                sp[cl * TB + r]      = s1a * s2a;
                sp[cl * TB + r + 32] = s1b * s2b;
            }
        } else {
            int nw = Cn * TB;
            for (int p = tid; p < nw; p += NTHR) {
                int cl = p >> 6;
                int r  = p & 63;
                int c  = ck0 + cl;
                size_t rowoff = (size_t)(b0 + r) * DIM;

                float s1 = 0.0f;
                int e0 = __ldg(&g_cp1[c]), e1 = __ldg(&g_cp1[c + 1]);
                for (int e = e0; e < e1; e++) {
                    unsigned u = __ldg(&g_ent1[e]);
                    float x = __ldg(&x1[rowoff + (u & 1023u)]);
                    s1 += (u & 0x8000u) ? -x : x;
                }
                float s2 = 0.0f;
                int f0 = __ldg(&g_cp2[c]), f1 = __ldg(&g_cp2[c + 1]);
                for (int e = f0; e < f1; e++) {
                    unsigned u = __ldg(&g_ent2[e]);
                    float x = __ldg(&x2[rowoff + (u & 1023u)]);
                    s2 += (u & 0x8000u) ? -x : x;
                }
                sp[cl * TB + r] = s1 * s2;
            }
        }
        cpasync_wait0();              // sub-tile 0 landed (long since)
        __syncthreads();              // sp + WSbuf[0] visible to all

        // ---- GEMM pipeline over sub-tiles ----
        for (int sub = 0; sub < nsub; sub++) {
            if (sub + 1 < nsub) {     // issue next sub-tile into other buffer
                int cidx = ck0 + (sub + 1) * SUBCL + st_row;
                if (cidx >= m) cidx = m - 1;
                int wrow = __ldg(&g_colJ[cidx]);
                const float* src = W + (size_t)wrow * OUT + st_col;
                unsigned int dst = (unsigned int)__cvta_generic_to_shared(
                                       WSbuf[(sub + 1) & 1] + st_row * OUT + st_col);
                cpasync16(dst,      src);
                cpasync16(dst + 16, src + 4);
                cpasync16(dst + 32, src + 8);
                cpasync16(dst + 48, src + 12);
                cpasync_commit();
            }

            const float* wsb = WSbuf[sub & 1];
            int base = sub * SUBCL;
            int Csub = min(SUBCL, Cn - base);
            if (Csub == SUBCL) {
#pragma unroll 8
                for (int c2 = 0; c2 < SUBCL; c2++) GEMM_STEP(wsb, base, c2)
            } else {
                for (int c2 = 0; c2 < Csub; c2++) GEMM_STEP(wsb, base, c2)
            }

            if (sub + 1 < nsub) cpasync_wait0();
            __syncthreads();          // buffer handoff / sp reuse
        }
    }

    // -------- LayerNorm: reduce each row across the 32 warps ---------------
    float* red_s = sp;                   // [64][33], aliases product tile
    float* red_q = sp + TB * 33;
#pragma unroll
    for (int p = 0; p < 2; p++) {
        float s = 0.0f, q = 0.0f;
#pragma unroll
        for (int k = 0; k < 8; k++) {
            float lo, hi;
            unpack2(acc2[p][k], lo, hi);
            s += lo + hi;
            q += lo * lo + hi * hi;
        }
        red_s[(r0 + p) * 33 + wrp] = s;
        red_q[(r0 + p) * 33 + wrp] = q;
    }
    __syncthreads();

    float* shmu = WSbuf[0];              // aliases W staging buffer
    float* shrs = WSbuf[0] + TB;
    if (tid < TB) {
        float s = 0.0f, q = 0.0f;
#pragma unroll
        for (int w = 0; w < 32; w++) {
            s += red_s[tid * 33 + w];
            q += red_q[tid * 33 + w];
        }
        float mu  = s * (1.0f / OUT);
        float var = q * (1.0f / OUT) - mu * mu;
        shmu[tid] = mu;
        shrs[tid] = rsqrtf(var + LN_EPS);
    }
    __syncthreads();

    // -------- normalize, affine, ReLU, store -------------------------------
#pragma unroll
    for (int p = 0; p < 2; p++) {
        int row = r0 + p;
        float mu = shmu[row];
        float rs = shrs[row];
        float* dst = out + (size_t)(b0 + row) * OUT + o0;
#pragma unroll
        for (int q = 0; q < 4; q++) {
            float4 g4 = __ldg((const float4*)(gamma + o0 + 4 * q));
            float4 e4 = __ldg((const float4*)(beta  + o0 + 4 * q));
            float lo0, hi0, lo1, hi1;
            unpack2(acc2[p][2 * q],     lo0, hi0);
            unpack2(acc2[p][2 * q + 1], lo1, hi1);
            float4 o4;
            o4.x = fmaxf((lo0 - mu) * rs * g4.x + e4.x, 0.0f);
            o4.y = fmaxf((hi0 - mu) * rs * g4.y + e4.y, 0.0f);
            o4.z = fmaxf((lo1 - mu) * rs * g4.z + e4.z, 0.0f);
            o4.w = fmaxf((hi1 - mu) * rs * g4.w + e4.w, 0.0f);
            *(float4*)(dst + 4 * q) = o4;
        }
    }
}

// ---------------------------------------------------------------------------
extern "C" void kernel_launch(void* const* d_in, const int* in_sizes, int n_in,
                              void* d_out, int out_size)
{
    const float* x1    = (const float*)d_in[0];
    const float* x2    = (const float*)d_in[1];
    const float* S1    = (const float*)d_in[2];
    const float* S2    = (const float*)d_in[3];
    const float* W     = (const float*)d_in[4];
    const float* b     = (const float*)d_in[5];
    const float* gamma = (const float*)d_in[6];
    const float* beta  = (const float*)d_in[7];
    float* out = (float*)d_out;

    // attribute set (not an allocation); idempotent and graph-legal
    cudaFuncSetAttribute(k_main, cudaFuncAttributeMaxDynamicSharedMemorySize,
                         DSM_BYTES);

    k_extract<<<2 * DIM, 256>>>(S1, S2);
    k_build<<<1, 1024>>>();
    k_main<<<BATCH / TB, NTHR, DSM_BYTES>>>(x1, x2, W, b, gamma, beta, out);
}

// round 12
// speedup vs baseline: 1.3549x; 1.3549x over previous
#include <cuda_runtime.h>
#include <cuda_bf16.h>
#include <cstdint>
#include <math.h>

// Problem constants
#define BATCH   8192
#define DIM     1024      // DIM1 == DIM2
#define SKETCH  8192
#define OUT     512
#define LN_EPS  1e-5f

#define MCAP    1024      // |J| <= 1024 (hard bound)
#define CCH     128       // column chunk for main kernel
#define TB      64        // batch rows per CTA in main kernel
#define NTHR    1024      // threads per CTA (32 warps)
#define SUBCL   32        // W staging sub-chunk (32 cols x 512 x 4B = 64KB)

// dynamic smem layout (floats): sp[CCH*TB] (32KB) + WS[SUBCL*OUT] (64KB)
#define SP_OFF     0
#define WS_OFF     (CCH * TB)
#define DSM_FLOATS (WS_OFF + SUBCL * OUT)
#define DSM_BYTES  (DSM_FLOATS * 4)          // 96 KB

// ---------------- device globals (scratch; no cudaMalloc allowed) ----------
__device__ unsigned int g_idx1[DIM];
__device__ unsigned int g_idx2[DIM];
__device__ int          g_m;
__device__ int          g_fallback;       // 1 if any column has >4 entries
__device__ int          g_colJ[MCAP];
__device__ int          g_cp1[MCAP + 1];
__device__ int          g_cp2[MCAP + 1];
__device__ unsigned int g_ent1[MCAP];     // (sign<<15) | i
__device__ unsigned int g_ent2[MCAP];
__device__ ulonglong2   g_rec[MCAP];      // packed per-column records
__device__ float        g_Wc[MCAP * OUT]; // compacted W rows

// -------- f32x2 packed-FMA helpers (PTX-only) ------------------------------
__device__ __forceinline__ unsigned long long pack2(float lo, float hi) {
    unsigned long long r;
    asm("mov.b64 %0, {%1, %2};" : "=l"(r) : "f"(lo), "f"(hi));
    return r;
}
__device__ __forceinline__ void unpack2(unsigned long long v, float& lo, float& hi) {
    asm("mov.b64 {%0, %1}, %2;" : "=f"(lo), "=f"(hi) : "l"(v));
}
__device__ __forceinline__ unsigned long long ffma2(unsigned long long a,
                                                    unsigned long long b,
                                                    unsigned long long c) {
    unsigned long long d;
    asm("fma.rn.f32x2 %0, %1, %2, %3;" : "=l"(d) : "l"(a), "l"(b), "l"(c));
    return d;
}
// apply packed sign: e bit10 set -> negate (XOR into fp32 sign bit)
__device__ __forceinline__ float sgnapply(float x, unsigned e) {
    return __int_as_float(__float_as_int(x) ^ (int)((e & 1024u) << 21));
}

// -------- warp-shuffle block scan (1024 threads) ---------------------------
__device__ __forceinline__ int block_scan_incl(int val, int t, int* ws) {
    const unsigned full = 0xFFFFFFFFu;
    int lane = t & 31;
#pragma unroll
    for (int o = 1; o < 32; o <<= 1) {
        int n = __shfl_up_sync(full, val, o);
        if (lane >= o) val += n;
    }
    if (lane == 31) ws[t >> 5] = val;
    __syncthreads();
    if (t < 32) {
        int v = ws[t];
#pragma unroll
        for (int o = 1; o < 32; o <<= 1) {
            int n = __shfl_up_sync(full, v, o);
            if (t >= o) v += n;
        }
        ws[t] = v;
    }
    __syncthreads();
    if (t >= 32) val += ws[(t >> 5) - 1];
    return val;
}

// ---------------------------------------------------------------------------
// Kernel A: find the single nonzero per row of S1/S2. Coalesced float4 scan.
// ---------------------------------------------------------------------------
__global__ void k_extract(const float* __restrict__ S1,
                          const float* __restrict__ S2)
{
    int row = blockIdx.x;
    const float* S;
    unsigned int* outp;
    if (row < DIM) { S = S1; outp = g_idx1; }
    else           { S = S2; outp = g_idx2; row -= DIM; }

    const float4* p = (const float4*)(S + (size_t)row * SKETCH);
    int t = threadIdx.x;
#pragma unroll
    for (int k = 0; k < SKETCH / 4 / 256; k++) {
        int v4 = t + k * 256;
        float4 v = p[v4];
        int base = v4 * 4;
        if (v.x != 0.0f) outp[row] = (unsigned)(base + 0) | (v.x < 0.0f ? 0x80000000u : 0u);
        if (v.y != 0.0f) outp[row] = (unsigned)(base + 1) | (v.y < 0.0f ? 0x80000000u : 0u);
        if (v.z != 0.0f) outp[row] = (unsigned)(base + 2) | (v.z < 0.0f ? 0x80000000u : 0u);
        if (v.w != 0.0f) outp[row] = (unsigned)(base + 3) | (v.w < 0.0f ? 0x80000000u : 0u);
    }
}

// ---------------------------------------------------------------------------
// Kernel B: build compact structure + CSR + packed records. 1 CTA, 1024 thr.
// ---------------------------------------------------------------------------
__global__ void k_build()
{
    __shared__ int cnt[SKETCH];      // occupancy counts, then colmap
    __shared__ int colcnt[MCAP];
    __shared__ int ws[32];
    __shared__ int sh_total;

    int t = threadIdx.x;

    for (int j = t; j < SKETCH; j += 1024) cnt[j] = 0;
    if (t == 0) g_fallback = 0;
    __syncthreads();

    unsigned u1 = g_idx1[t];
    unsigned u2 = g_idx2[t];
    atomicAdd(&cnt[u1 & (SKETCH - 1)], 1);
    atomicAdd(&cnt[u2 & (SKETCH - 1)], 1 << 16);
    __syncthreads();

    int q = 0;
    int qual[8];
#pragma unroll
    for (int u = 0; u < 8; u++) {
        int j = t * 8 + u;
        int c = cnt[j];
        qual[u] = ((c & 0xFFFF) > 0 && (c >> 16) > 0) ? 1 : 0;
        q += qual[u];
    }
    int incl = block_scan_incl(q, t, ws);
    int excl = incl - q;
    if (t == 1023) sh_total = incl;
    __syncthreads();
    int total = sh_total;

#pragma unroll
    for (int u = 0; u < 8; u++) {
        int j = t * 8 + u;
        if (qual[u]) { g_colJ[excl] = j; cnt[j] = excl; excl++; }
        else         { cnt[j] = -1; }
    }
    if (t == 0) g_m = total;
    __syncthreads();

    int c1 = cnt[u1 & (SKETCH - 1)];
    int c2 = cnt[u2 & (SKETCH - 1)];
#pragma unroll
    for (int s = 0; s < 2; s++) {
        int cc = s ? c2 : c1;
        unsigned uu = s ? u2 : u1;
        int* cp = s ? g_cp2 : g_cp1;
        unsigned int* ent = s ? g_ent2 : g_ent1;

        colcnt[t] = 0;
        __syncthreads();
        if (cc >= 0) atomicAdd(&colcnt[cc], 1);
        __syncthreads();

        int myc = colcnt[t];
        int inc2 = block_scan_incl(myc, t, ws);
        int ex = inc2 - myc;
        cp[t] = ex;
        if (t == 1023) cp[1024] = inc2;
        __syncthreads();
        colcnt[t] = ex;
        __syncthreads();
        if (cc >= 0) {
            int slot = atomicAdd(&colcnt[cc], 1);
            ent[slot] = (((uu >> 31) & 1u) << 15) | (unsigned)t;
        }
        __syncthreads();
    }

    // ---- packed records: per column, both sides, up to 4 entries ----
    if (t < total) {
        unsigned long long w[2];
#pragma unroll
        for (int s = 0; s < 2; s++) {
            const int* cp = s ? g_cp2 : g_cp1;
            const unsigned int* ent = s ? g_ent2 : g_ent1;
            int e0 = cp[t], e1 = cp[t + 1];
            int cnte = e1 - e0;
            if (cnte > 4) { atomicOr(&g_fallback, 1); cnte = 4; }
            unsigned long long u = 0;
            for (int k = 0; k < cnte; k++) {
                unsigned v = ent[e0 + k];
                unsigned i = v & 1023u;
                unsigned sg = (v >> 15) & 1u;
                u |= (unsigned long long)(i | (sg << 10)) << (11 * k);
            }
            u |= (unsigned long long)cnte << 60;
            w[s] = u;
        }
        ulonglong2 r;
        r.x = w[0];
        r.y = w[1];
        g_rec[t] = r;
    }
}

// ---------------------------------------------------------------------------
// Kernel B2: gather compacted W rows (proven; keeps k_main's staging simple
// and perfectly coalesced from a contiguous buffer).
// ---------------------------------------------------------------------------
__global__ void k_wgather(const float* __restrict__ W)
{
    int c = blockIdx.x;
    if (c < g_m) {
        g_Wc[(size_t)c * OUT + threadIdx.x] =
            W[(size_t)g_colJ[c] * OUT + threadIdx.x];
    }
}

// ---------------------------------------------------------------------------
// GEMM micro-step (proven round-7/9 inner loop)
// ---------------------------------------------------------------------------
#define GEMM_STEP(base, c2_)                                                   \
    {                                                                          \
        float2 vv = *(const float2*)&sp[((base) + (c2_)) * TB + r0];           \
        unsigned long long v2a = pack2(vv.x, vv.x);                            \
        unsigned long long v2b = pack2(vv.y, vv.y);                            \
        const ulonglong2* wp = (const ulonglong2*)&WS[(c2_) * OUT + o0];       \
        ulonglong2 w01 = wp[0];                                                \
        ulonglong2 w23 = wp[1];                                                \
        ulonglong2 w45 = wp[2];                                                \
        ulonglong2 w67 = wp[3];                                                \
        acc2[0][0] = ffma2(v2a, w01.x, acc2[0][0]);                            \
        acc2[1][0] = ffma2(v2b, w01.x, acc2[1][0]);                            \
        acc2[0][1] = ffma2(v2a, w01.y, acc2[0][1]);                            \
        acc2[1][1] = ffma2(v2b, w01.y, acc2[1][1]);                            \
        acc2[0][2] = ffma2(v2a, w23.x, acc2[0][2]);                            \
        acc2[1][2] = ffma2(v2b, w23.x, acc2[1][2]);                            \
        acc2[0][3] = ffma2(v2a, w23.y, acc2[0][3]);                            \
        acc2[1][3] = ffma2(v2b, w23.y, acc2[1][3]);                            \
        acc2[0][4] = ffma2(v2a, w45.x, acc2[0][4]);                            \
        acc2[1][4] = ffma2(v2b, w45.x, acc2[1][4]);                            \
        acc2[0][5] = ffma2(v2a, w45.y, acc2[0][5]);                            \
        acc2[1][5] = ffma2(v2b, w45.y, acc2[1][5]);                            \
        acc2[0][6] = ffma2(v2a, w67.x, acc2[0][6]);                            \
        acc2[1][6] = ffma2(v2b, w67.x, acc2[1][6]);                            \
        acc2[0][7] = ffma2(v2a, w67.y, acc2[0][7]);                            \
        acc2[1][7] = ffma2(v2b, w67.y, acc2[1][7]);                            \
    }

// ---------------------------------------------------------------------------
// Main fused kernel. TB=64 rows/CTA, 1024 threads (32 warps), 128 CTAs.
//  Gather: packed records, 2 rows/thread (round-9 proven path).
//  GEMM: W staged to smem per 32-col sub-tile (synchronous, perfectly
//  coalesced: lane-consecutive float4), warp-uniform broadcast LDS,
//  fma.rn.f32x2, warp=16 cols x lane=2 rows.
//  Epilogue: LayerNorm (bias folded into acc init) + ReLU.
// ---------------------------------------------------------------------------
__global__ void __launch_bounds__(NTHR, 1)
k_main(const float* __restrict__ x1, const float* __restrict__ x2,
       const float* __restrict__ bias, const float* __restrict__ gamma,
       const float* __restrict__ beta, float* __restrict__ out)
{
    extern __shared__ __align__(16) float dsm[];
    float* sp = dsm + SP_OFF;     // [CCH][TB] product tile; LN bufs alias
    float* WS = dsm + WS_OFF;     // [SUBCL][OUT] W staging; mu/rs alias

    int tid  = threadIdx.x;
    int lane = tid & 31;
    int wrp  = tid >> 5;          // 0..31 -> cols [wrp*16, wrp*16+16)
    int o0   = wrp * 16;
    int r0   = lane * 2;          // rows r0, r0+1
    int b0   = blockIdx.x * TB;

    int m  = g_m;
    int fb = g_fallback;

    // accumulators: acc2[p][k] = row (r0+p), cols (o0+2k, o0+2k+1)
    unsigned long long acc2[2][8];
    {
        const ulonglong2* bq = (const ulonglong2*)(bias + o0);
#pragma unroll
        for (int q = 0; q < 4; q++) {
            ulonglong2 bb = __ldg(bq + q);
            acc2[0][2 * q]     = bb.x;
            acc2[0][2 * q + 1] = bb.y;
            acc2[1][2 * q]     = bb.x;
            acc2[1][2 * q + 1] = bb.y;
        }
    }

    int nch = (m + CCH - 1) / CCH;
    for (int ch = 0; ch < nch; ch++) {
        int ck0 = ch * CCH;
        int Cn  = min(CCH, m - ck0);

        // ---- gather: v[c][r] = s1(c,r) * s2(c,r) ----
        if (!fb) {
            int nw = Cn * 32;
            for (int p = tid; p < nw; p += NTHR) {
                int cl = p >> 5;
                int r  = p & 31;
                int c  = ck0 + cl;
                ulonglong2 rec = __ldg(&g_rec[c]);
                size_t ro0 = (size_t)(b0 + r) * DIM;
                size_t ro1 = (size_t)(b0 + r + 32) * DIM;

                unsigned long long u = rec.x;
                int cnt1 = (int)(u >> 60);
                unsigned e = (unsigned)u & 0x7FFu;
                float s1a = sgnapply(__ldg(&x1[ro0 + (e & 1023u)]), e);
                float s1b = sgnapply(__ldg(&x1[ro1 + (e & 1023u)]), e);
#pragma unroll
                for (int k = 1; k < 4; k++) {
                    if (k < cnt1) {
                        e = (unsigned)(u >> (11 * k)) & 0x7FFu;
                        s1a += sgnapply(__ldg(&x1[ro0 + (e & 1023u)]), e);
                        s1b += sgnapply(__ldg(&x1[ro1 + (e & 1023u)]), e);
                    }
                }
                u = rec.y;
                int cnt2 = (int)(u >> 60);
                e = (unsigned)u & 0x7FFu;
                float s2a = sgnapply(__ldg(&x2[ro0 + (e & 1023u)]), e);
                float s2b = sgnapply(__ldg(&x2[ro1 + (e & 1023u)]), e);
#pragma unroll
                for (int k = 1; k < 4; k++) {
                    if (k < cnt2) {
                        e = (unsigned)(u >> (11 * k)) & 0x7FFu;
                        s2a += sgnapply(__ldg(&x2[ro0 + (e & 1023u)]), e);
                        s2b += sgnapply(__ldg(&x2[ro1 + (e & 1023u)]), e);
                    }
                }
                sp[cl * TB + r]      = s1a * s2a;
                sp[cl * TB + r + 32] = s1b * s2b;
            }
        } else {
            int nw = Cn * TB;
            for (int p = tid; p < nw; p += NTHR) {
                int cl = p >> 6;
                int r  = p & 63;
                int c  = ck0 + cl;
                size_t rowoff = (size_t)(b0 + r) * DIM;

                float s1 = 0.0f;
                int e0 = __ldg(&g_cp1[c]), e1 = __ldg(&g_cp1[c + 1]);
                for (int e = e0; e < e1; e++) {
                    unsigned u = __ldg(&g_ent1[e]);
                    float x = __ldg(&x1[rowoff + (u & 1023u)]);
                    s1 += (u & 0x8000u) ? -x : x;
                }
                float s2 = 0.0f;
                int f0 = __ldg(&g_cp2[c]), f1 = __ldg(&g_cp2[c + 1]);
                for (int e = f0; e < f1; e++) {
                    unsigned u = __ldg(&g_ent2[e]);
                    float x = __ldg(&x2[rowoff + (u & 1023u)]);
                    s2 += (u & 0x8000u) ? -x : x;
                }
                sp[cl * TB + r] = s1 * s2;
            }
        }
        __syncthreads();

        // ---- GEMM over sub-chunks: stage 32 W rows to smem, then FFMA2 ----
        int nsub = (Cn + SUBCL - 1) / SUBCL;
        for (int sub = 0; sub < nsub; sub++) {
            {   // stage W: 32 rows x 512 floats, 4 float4 per thread,
                // lane-consecutive -> perfectly coalesced (4 wavefronts/LDG)
                int row = tid >> 5;              // 0..31
                int f4  = tid & 31;              // lane-consecutive float4 id
                const float4* src = (const float4*)
                    &g_Wc[(size_t)(ck0 + sub * SUBCL + row) * OUT];
                float4* dstW = (float4*)&WS[row * OUT];
#pragma unroll
                for (int k = 0; k < 4; k++)
                    dstW[f4 + k * 32] = __ldg(&src[f4 + k * 32]);
            }
            __syncthreads();

            int base = sub * SUBCL;
            int Csub = min(SUBCL, Cn - base);
            if (Csub == SUBCL) {
#pragma unroll 8
                for (int c2 = 0; c2 < SUBCL; c2++) GEMM_STEP(base, c2)
            } else {
                for (int c2 = 0; c2 < Csub; c2++) GEMM_STEP(base, c2)
            }
            __syncthreads();   // WS (and, on last sub, sp) about to be reused
        }
    }

    // -------- LayerNorm: reduce each row across the 32 warps ---------------
    float* red_s = sp;                   // [64][33], aliases product tile
    float* red_q = sp + TB * 33;
#pragma unroll
    for (int p = 0; p < 2; p++) {
        float s = 0.0f, q = 0.0f;
#pragma unroll
        for (int k = 0; k < 8; k++) {
            float lo, hi;
            unpack2(acc2[p][k], lo, hi);
            s += lo + hi;
            q += lo * lo + hi * hi;
        }
        red_s[(r0 + p) * 33 + wrp] = s;
        red_q[(r0 + p) * 33 + wrp] = q;
    }
    __syncthreads();

    float* shmu = WS;                    // aliases W staging buffer
    float* shrs = WS + TB;
    if (tid < TB) {
        float s = 0.0f, q = 0.0f;
#pragma unroll
        for (int w = 0; w < 32; w++) {
            s += red_s[tid * 33 + w];
            q += red_q[tid * 33 + w];
        }
        float mu  = s * (1.0f / OUT);
        float var = q * (1.0f / OUT) - mu * mu;
        shmu[tid] = mu;
        shrs[tid] = rsqrtf(var + LN_EPS);
    }
    __syncthreads();

    // -------- normalize, affine, ReLU, store -------------------------------
#pragma unroll
    for (int p = 0; p < 2; p++) {
        int row = r0 + p;
        float mu = shmu[row];
        float rs = shrs[row];
        float* dst = out + (size_t)(b0 + row) * OUT + o0;
#pragma unroll
        for (int q = 0; q < 4; q++) {
            float4 g4 = __ldg((const float4*)(gamma + o0 + 4 * q));
            float4 e4 = __ldg((const float4*)(beta  + o0 + 4 * q));
            float lo0, hi0, lo1, hi1;
            unpack2(acc2[p][2 * q],     lo0, hi0);
            unpack2(acc2[p][2 * q + 1], lo1, hi1);
            float4 o4;
            o4.x = fmaxf((lo0 - mu) * rs * g4.x + e4.x, 0.0f);
            o4.y = fmaxf((hi0 - mu) * rs * g4.y + e4.y, 0.0f);
            o4.z = fmaxf((lo1 - mu) * rs * g4.z + e4.z, 0.0f);
            o4.w = fmaxf((hi1 - mu) * rs * g4.w + e4.w, 0.0f);
            *(float4*)(dst + 4 * q) = o4;
        }
    }
}

// ---------------------------------------------------------------------------
extern "C" void kernel_launch(void* const* d_in, const int* in_sizes, int n_in,
                              void* d_out, int out_size)
{
    const float* x1    = (const float*)d_in[0];
    const float* x2    = (const float*)d_in[1];
    const float* S1    = (const float*)d_in[2];
    const float* S2    = (const float*)d_in[3];
    const float* W     = (const float*)d_in[4];
    const float* b     = (const float*)d_in[5];
    const float* gamma = (const float*)d_in[6];
    const float* beta  = (const float*)d_in[7];
    float* out = (float*)d_out;

    // attribute set (not an allocation); idempotent and graph-legal
    cudaFuncSetAttribute(k_main, cudaFuncAttributeMaxDynamicSharedMemorySize,
                         DSM_BYTES);

    k_extract<<<2 * DIM, 256>>>(S1, S2);
    k_build<<<1, 1024>>>();
    k_wgather<<<MCAP, OUT>>>(W);
    k_main<<<BATCH / TB, NTHR, DSM_BYTES>>>(x1, x2, b, gamma, beta, out);
}